// round 4
// baseline (speedup 1.0000x reference)
#include <cuda_runtime.h>

// Problem constants (from reference setup_inputs)
#define B 8
#define H 100
#define W 100
#define C 512
#define R 300
#define POOL 7
#define NCELL (R * POOL * POOL)   // 14700
#define HB (B / 2)                // batch pairs: (b, b+4)

// Precomputed per-(roi, cell) data, batch-independent.
__device__ int4   g_offs[NCELL];   // element offsets of tl, tr, bl, br within one batch slice
__device__ float4 g_wts[NCELL];    // bilinear weights w_tl, w_tr, w_bl, w_br

__global__ void precompute_kernel(const int* __restrict__ rois)
{
    int i = blockIdx.x * blockDim.x + threadIdx.x;
    if (i >= NCELL) return;

    int r    = i / 49;
    int cell = i - r * 49;
    int py   = cell / POOL;
    int px   = cell - py * POOL;

    const int4 roi = __ldg(((const int4*)rois) + r);
    const int x1 = roi.x, y1 = roi.y, w = roi.z, h = roi.w;

    // y axis (replicates JAX fp32 math)
    float sh = (float)h;
    float vy = ((float)py + 0.5f) * (sh / (float)POOL) - 0.5f;
    vy = fminf(fmaxf(vy, 0.0f), sh - 1.0f);
    float fly = floorf(vy);
    int   ylo = (int)fly;
    float fy  = vy - fly;
    int   yhi = min(ylo + 1, h - 1);
    int yl = y1 + ylo;
    int yh = y1 + yhi;

    // x axis
    float sw = (float)w;
    float vx = ((float)px + 0.5f) * (sw / (float)POOL) - 0.5f;
    vx = fminf(fmaxf(vx, 0.0f), sw - 1.0f);
    float flx = floorf(vx);
    int   xlo = (int)flx;
    float fx  = vx - flx;
    int   xhi = min(xlo + 1, w - 1);
    int xl = x1 + xlo;
    int xh = x1 + xhi;

    int4 o;
    o.x = (yl * W + xl) * C;   // tl
    o.y = (yl * W + xh) * C;   // tr
    o.z = (yh * W + xl) * C;   // bl
    o.w = (yh * W + xh) * C;   // br
    g_offs[i] = o;

    float gx = 1.0f - fx;
    float gy = 1.0f - fy;
    float4 wt;
    wt.x = gx * gy;   // tl
    wt.y = fx * gy;   // tr
    wt.z = gx * fy;   // bl
    wt.w = fx * fy;   // br
    g_wts[i] = wt;
}

// grid: (R*7, B/2). One block per (roi, py) row, processing batches b and b+4.
// 128 threads * float4 = 512 channels. One-cell-ahead software prefetch; each
// iteration has 8 independent LDG.128 in flight plus the prefetched stage.
__global__ __launch_bounds__(128) void roi_align_kernel(
    const float* __restrict__ x,    // (B, H, W, C)
    float*       __restrict__ out)  // (B, R, 7, 7, C)
{
    const int rp = blockIdx.x;      // r*7 + py
    const int ib = blockIdx.y;      // batch pair: (ib, ib+4)
    const int i0 = rp * POOL;       // first cell index of this row

    const int c = threadIdx.x * 4;
    const float* base0 = x + (size_t)ib * (H * W * C);
    const float* base1 = base0 + (size_t)HB * (H * W * C);
    float* po0 = out + ((size_t)ib * NCELL + i0) * C + c;
    float* po1 = po0 + (size_t)HB * NCELL * C;

    // Prologue: load corners for px = 0, both batches (8 loads in flight)
    int4 o4 = g_offs[i0];
    float4 tl0 = *(const float4*)(base0 + o4.x + c);
    float4 tr0 = *(const float4*)(base0 + o4.y + c);
    float4 bl0 = *(const float4*)(base0 + o4.z + c);
    float4 br0 = *(const float4*)(base0 + o4.w + c);
    float4 tl1 = *(const float4*)(base1 + o4.x + c);
    float4 tr1 = *(const float4*)(base1 + o4.y + c);
    float4 bl1 = *(const float4*)(base1 + o4.z + c);
    float4 br1 = *(const float4*)(base1 + o4.w + c);

    #pragma unroll
    for (int px = 0; px < POOL; ++px) {
        const float4 wt = g_wts[i0 + px];

        // retire current stage into locals
        const float4 ctl0 = tl0, ctr0 = tr0, cbl0 = bl0, cbr0 = br0;
        const float4 ctl1 = tl1, ctr1 = tr1, cbl1 = bl1, cbr1 = br1;

        // prefetch next stage (both batches) before consuming current
        if (px < POOL - 1) {
            const int4 n4 = g_offs[i0 + px + 1];
            tl0 = *(const float4*)(base0 + n4.x + c);
            tr0 = *(const float4*)(base0 + n4.y + c);
            bl0 = *(const float4*)(base0 + n4.z + c);
            br0 = *(const float4*)(base0 + n4.w + c);
            tl1 = *(const float4*)(base1 + n4.x + c);
            tr1 = *(const float4*)(base1 + n4.y + c);
            bl1 = *(const float4*)(base1 + n4.z + c);
            br1 = *(const float4*)(base1 + n4.w + c);
        }

        float4 o0, o1;
        o0.x = fmaf(cbr0.x, wt.w, fmaf(cbl0.x, wt.z, fmaf(ctr0.x, wt.y, ctl0.x * wt.x)));
        o0.y = fmaf(cbr0.y, wt.w, fmaf(cbl0.y, wt.z, fmaf(ctr0.y, wt.y, ctl0.y * wt.x)));
        o0.z = fmaf(cbr0.z, wt.w, fmaf(cbl0.z, wt.z, fmaf(ctr0.z, wt.y, ctl0.z * wt.x)));
        o0.w = fmaf(cbr0.w, wt.w, fmaf(cbl0.w, wt.z, fmaf(ctr0.w, wt.y, ctl0.w * wt.x)));
        o1.x = fmaf(cbr1.x, wt.w, fmaf(cbl1.x, wt.z, fmaf(ctr1.x, wt.y, ctl1.x * wt.x)));
        o1.y = fmaf(cbr1.y, wt.w, fmaf(cbl1.y, wt.z, fmaf(ctr1.y, wt.y, ctl1.y * wt.x)));
        o1.z = fmaf(cbr1.z, wt.w, fmaf(cbl1.z, wt.z, fmaf(ctr1.z, wt.y, ctl1.z * wt.x)));
        o1.w = fmaf(cbr1.w, wt.w, fmaf(cbl1.w, wt.z, fmaf(ctr1.w, wt.y, ctl1.w * wt.x)));

        // output is never re-read: streaming stores
        __stcs((float4*)(po0 + px * C), o0);
        __stcs((float4*)(po1 + px * C), o1);
    }
}

extern "C" void kernel_launch(void* const* d_in, const int* in_sizes, int n_in,
                              void* d_out, int out_size)
{
    const float* x    = (const float*)d_in[0];
    const int*   rois = (const int*)d_in[1];
    float*       out  = (float*)d_out;

    precompute_kernel<<<(NCELL + 127) / 128, 128>>>(rois);

    dim3 grid(R * POOL, HB);   // 8,400 blocks
    roi_align_kernel<<<grid, 128>>>(x, out);
}

// round 5
// speedup vs baseline: 1.0846x; 1.0846x over previous
#include <cuda_runtime.h>

// Problem constants (from reference setup_inputs)
#define B 8
#define H 100
#define W 100
#define C 512
#define R 300
#define POOL 7

// grid: (R, POOL, B). One block per (roi, py) row of 7 px cells for one batch.
// 128 threads * float4 = 512 channels. All coordinate math inline (uniform per
// block / per iteration) — no precompute kernel, no table loads.
__global__ __launch_bounds__(128) void roi_align_kernel(
    const float* __restrict__ x,     // (B, H, W, C)
    const int*   __restrict__ rois,  // (R, 4): x1, y1, w, h
    float*       __restrict__ out)   // (B, R, 7, 7, C)
{
    const int r  = blockIdx.x;
    const int py = blockIdx.y;
    const int b  = blockIdx.z;

    const int4 roi = __ldg(((const int4*)rois) + r);
    const int x1 = roi.x, y1 = roi.y, w = roi.z, h = roi.w;

    // --- y axis coords, once per block (replicates JAX fp32 math) ---
    const float sh = (float)h;
    float vy = ((float)py + 0.5f) * (sh * (1.0f / POOL)) - 0.5f;
    vy = fminf(fmaxf(vy, 0.0f), sh - 1.0f);
    const float fly = floorf(vy);
    const int   ylo = (int)fly;
    const float fy  = vy - fly;
    const int   yhi = min(ylo + 1, h - 1);
    const int yl = y1 + ylo;
    const int yh = y1 + yhi;

    // x-axis common subexpressions
    const float sw   = (float)w;
    const float stpx = sw * (1.0f / POOL);
    const float clx  = sw - 1.0f;
    const int   xmax = w - 1;

    const int c = threadIdx.x * 4;
    const float* base  = x + ((size_t)b * H * W) * C + c;
    const float* rowl  = base + (size_t)yl * (W * C);
    const float* rowh  = base + (size_t)yh * (W * C);
    float* po = out + (((size_t)(b * R + r) * POOL + py) * POOL) * C + c;

    const float gy = 1.0f - fy;

    #pragma unroll
    for (int px = 0; px < POOL; ++px) {
        // --- x axis coords for this cell ---
        float vx = ((float)px + 0.5f) * stpx - 0.5f;
        vx = fminf(fmaxf(vx, 0.0f), clx);
        float flx = floorf(vx);
        int   xlo = (int)flx;
        float fx  = vx - flx;
        int   xhi = min(xlo + 1, xmax);
        int xl = x1 + xlo;
        int xh = x1 + xhi;

        // 4 independent LDG.128, batched
        float4 tl = *(const float4*)(rowl + (size_t)xl * C);
        float4 tr = *(const float4*)(rowl + (size_t)xh * C);
        float4 bl = *(const float4*)(rowh + (size_t)xl * C);
        float4 br = *(const float4*)(rowh + (size_t)xh * C);

        // bilinear weights
        const float gx = 1.0f - fx;
        const float w_tl = gx * gy;
        const float w_tr = fx * gy;
        const float w_bl = gx * fy;
        const float w_br = fx * fy;

        float4 o;
        o.x = fmaf(br.x, w_br, fmaf(bl.x, w_bl, fmaf(tr.x, w_tr, tl.x * w_tl)));
        o.y = fmaf(br.y, w_br, fmaf(bl.y, w_bl, fmaf(tr.y, w_tr, tl.y * w_tl)));
        o.z = fmaf(br.z, w_br, fmaf(bl.z, w_bl, fmaf(tr.z, w_tr, tl.z * w_tl)));
        o.w = fmaf(br.w, w_br, fmaf(bl.w, w_bl, fmaf(tr.w, w_tr, tl.w * w_tl)));

        // output is never re-read: streaming store
        __stcs((float4*)(po + px * C), o);
    }
}

extern "C" void kernel_launch(void* const* d_in, const int* in_sizes, int n_in,
                              void* d_out, int out_size)
{
    const float* x    = (const float*)d_in[0];
    const int*   rois = (const int*)d_in[1];
    float*       out  = (float*)d_out;

    dim3 grid(R, POOL, B);   // 16,800 blocks; z-slowest => per-batch L2 locality
    roi_align_kernel<<<grid, 128>>>(x, rois, out);
}

// round 6
// speedup vs baseline: 1.1541x; 1.0640x over previous
#include <cuda_runtime.h>

// Problem constants (from reference setup_inputs)
#define B 8
#define H 100
#define W 100
#define C 512
#define R 300
#define POOL 7

// grid: (R, POOL, B). One block per (roi, py) row of 7 px cells for one batch.
// 128 threads * float4 = 512 channels. Inline coordinate math; 32-bit offsets;
// forced 16 CTAs/SM (regs <= 32) to maximize occupancy-carried MLP.
__global__ __launch_bounds__(128, 16) void roi_align_kernel(
    const float* __restrict__ x,     // (B, H, W, C)
    const int*   __restrict__ rois,  // (R, 4): x1, y1, w, h
    float*       __restrict__ out)   // (B, R, 7, 7, C)
{
    const int r  = blockIdx.x;
    const int py = blockIdx.y;
    const int b  = blockIdx.z;

    const int4 roi = __ldg(((const int4*)rois) + r);
    const int x1 = roi.x, y1 = roi.y, w = roi.z, h = roi.w;

    // --- y axis coords, once per block (replicates JAX fp32 math) ---
    const float sh = (float)h;
    float vy = fmaf((float)py + 0.5f, sh * (1.0f / POOL), -0.5f);
    vy = fminf(fmaxf(vy, 0.0f), sh - 1.0f);
    const float fly = floorf(vy);
    const int   ylo = (int)fly;
    const float fy  = vy - fly;
    const int   yhi = min(ylo + 1, h - 1);

    // x-axis common subexpressions
    const float sw   = (float)w;
    const float stpx = sw * (1.0f / POOL);
    const float clx  = sw - 1.0f;
    const int   xmax = w - 1;

    const int c = threadIdx.x * 4;

    // 32-bit element offsets (max < 2^31)
    const unsigned rowl_off = (unsigned)(b * (H * W) + (y1 + ylo) * W) * C + c;
    const unsigned rowh_off = (unsigned)(b * (H * W) + (y1 + yhi) * W) * C + c;
    const unsigned out_off  = (unsigned)(((b * R + r) * POOL + py) * POOL) * C + c;

    const float gy = 1.0f - fy;

    #pragma unroll
    for (int px = 0; px < POOL; ++px) {
        // --- x axis coords for this cell (px is a literal) ---
        float vx = fmaf((float)px + 0.5f, stpx, -0.5f);
        vx = fminf(fmaxf(vx, 0.0f), clx);
        float flx = floorf(vx);
        int   xlo = (int)flx;
        float fx  = vx - flx;
        int   xhi = min(xlo + 1, xmax);

        const unsigned ol = (unsigned)(x1 + xlo) * C;
        const unsigned oh = (unsigned)(x1 + xhi) * C;

        // 4 independent LDG.128
        float4 tl = *(const float4*)(x + rowl_off + ol);
        float4 tr = *(const float4*)(x + rowl_off + oh);
        float4 bl = *(const float4*)(x + rowh_off + ol);
        float4 br = *(const float4*)(x + rowh_off + oh);

        // bilinear weights
        const float gx = 1.0f - fx;
        const float w_tl = gx * gy;
        const float w_tr = fx * gy;
        const float w_bl = gx * fy;
        const float w_br = fx * fy;

        float4 o;
        o.x = fmaf(br.x, w_br, fmaf(bl.x, w_bl, fmaf(tr.x, w_tr, tl.x * w_tl)));
        o.y = fmaf(br.y, w_br, fmaf(bl.y, w_bl, fmaf(tr.y, w_tr, tl.y * w_tl)));
        o.z = fmaf(br.z, w_br, fmaf(bl.z, w_bl, fmaf(tr.z, w_tr, tl.z * w_tl)));
        o.w = fmaf(br.w, w_br, fmaf(bl.w, w_bl, fmaf(tr.w, w_tr, tl.w * w_tl)));

        // output is never re-read: streaming store
        __stcs((float4*)(out + out_off + (unsigned)px * C), o);
    }
}

extern "C" void kernel_launch(void* const* d_in, const int* in_sizes, int n_in,
                              void* d_out, int out_size)
{
    const float* x    = (const float*)d_in[0];
    const int*   rois = (const int*)d_in[1];
    float*       out  = (float*)d_out;

    dim3 grid(R, POOL, B);   // 16,800 blocks; z-slowest => per-batch L2 locality
    roi_align_kernel<<<grid, 128>>>(x, rois, out);
}